// round 11
// baseline (speedup 1.0000x reference)
#include <cuda_runtime.h>

// Problem constants
#define B_  64
#define S_  512
#define E_  256
#define H_  512
#define V_  50257
#define HS_STRIDE 513   // shared h row stride: 513 mod 32 == 1 -> conflict-free

// Scratch: device globals (the sanctioned allocation-free scratch)
__device__ float g_xproj[S_ * B_ * H_];     // [S][B][H]
__device__ float g_h[2][B_][H_];            // ping-pong hidden state

// ---------------------------------------------------------------------------
// Robust word fetch: the reference says int64 but JAX x64 is usually disabled,
// so the buffer may really be int32. Detect by checking the odd 32-bit halves
// (high words of little-endian int64s): random token ids are nonzero w.p.
// ~1-2e-5 each, so 4 zero high-halves => int64 layout.
// ---------------------------------------------------------------------------
__device__ __forceinline__ int words_is64(const int* w32) {
    return (w32[1] == 0) & (w32[3] == 0) & (w32[5] == 0) & (w32[7] == 0);
}
__device__ __forceinline__ unsigned int word_at(const int* w32, int i, int is64) {
    if (is64) {
        // little-endian int64, value < 2^31: low half carries the id
        return (unsigned int)w32[2 * i];
    }
    return (unsigned int)w32[i];
}

// ---------------------------------------------------------------------------
// Phase A: xproj[s][b][h] = bi[h] + sum_e emb[words[b][s]][e] * Wi[h][e]
// Tiled GEMM, 64(m) x 64(h) tiles, K=256 in 4 chunks of 64.
// 256 threads, each computes a 4x4 output block. Plain scalar indexing only.
// ---------------------------------------------------------------------------
__global__ __launch_bounds__(256) void xproj_kernel(
    const int* __restrict__ words,
    const float* __restrict__ emb,
    const float* __restrict__ Wi,
    const float* __restrict__ bi)
{
    __shared__ float As[64][65];
    __shared__ float Ws[64][65];
    __shared__ unsigned int wbase[64];

    const int t  = threadIdx.x;
    const int tx = t & 15;         // h sub-index
    const int ty = t >> 4;         // m sub-index
    const int h0 = blockIdx.x * 64;
    const int m0 = blockIdx.y * 64;

    if (t < 64) {
        int m = m0 + t;
        int s = m >> 6;
        int b = m & 63;            // m = s*64 + b
        int is64 = words_is64(words);
        unsigned int wid = word_at(words, b * S_ + s, is64);
        if (wid >= V_) wid = 0;    // safety clamp (should never fire)
        wbase[t] = wid * E_;
    }
    __syncthreads();

    float acc[4][4];
    #pragma unroll
    for (int i = 0; i < 4; i++)
        #pragma unroll
        for (int j = 0; j < 4; j++)
            acc[i][j] = 0.0f;

    for (int ec = 0; ec < 4; ec++) {
        // Stage 64x64 tiles of A (gathered emb rows) and Wi, coalesced scalar.
        #pragma unroll
        for (int i = 0; i < 16; i++) {
            int idx = t + 256 * i;         // 0..4095 over 64x64
            int rr  = idx >> 6;
            int cc  = idx & 63;
            As[rr][cc] = emb[wbase[rr] + ec * 64 + cc];
            Ws[rr][cc] = Wi[(h0 + rr) * E_ + ec * 64 + cc];
        }
        __syncthreads();

        #pragma unroll 8
        for (int e = 0; e < 64; e++) {
            float a0 = As[ty +  0][e];
            float a1 = As[ty + 16][e];
            float a2 = As[ty + 32][e];
            float a3 = As[ty + 48][e];
            float w0 = Ws[tx +  0][e];
            float w1 = Ws[tx + 16][e];
            float w2 = Ws[tx + 32][e];
            float w3 = Ws[tx + 48][e];
            acc[0][0] += a0 * w0; acc[0][1] += a0 * w1; acc[0][2] += a0 * w2; acc[0][3] += a0 * w3;
            acc[1][0] += a1 * w0; acc[1][1] += a1 * w1; acc[1][2] += a1 * w2; acc[1][3] += a1 * w3;
            acc[2][0] += a2 * w0; acc[2][1] += a2 * w1; acc[2][2] += a2 * w2; acc[2][3] += a2 * w3;
            acc[3][0] += a3 * w0; acc[3][1] += a3 * w1; acc[3][2] += a3 * w2; acc[3][3] += a3 * w3;
        }
        __syncthreads();
    }

    #pragma unroll
    for (int i = 0; i < 4; i++) {
        int m = m0 + ty + 16 * i;
        #pragma unroll
        for (int j = 0; j < 4; j++) {
            int h = h0 + tx + 16 * j;
            g_xproj[m * H_ + h] = acc[i][j] + bi[h];
        }
    }
}

// ---------------------------------------------------------------------------
// Phase B: one launch per timestep.
// Grid (8 batch-tiles, 16 row-tiles) x 256 threads.
// Thread t: b8 = t&7 (batch in tile), r = t>>3 (row in tile).
// Stages h[8 batches][512] in shared, then a plain 512-MAC dot per thread.
// ---------------------------------------------------------------------------
__global__ __launch_bounds__(256) void step_kernel(
    const float* __restrict__ Wh,
    const float* __restrict__ bh,
    float* __restrict__ out, int out_size, int s)
{
    __shared__ float hs[8 * HS_STRIDE];

    const int t  = threadIdx.x;
    const int bt = blockIdx.x;       // batch tile 0..7
    const int rt = blockIdx.y;       // row tile 0..15
    const int b8 = t & 7;
    const int r  = t >> 3;           // 0..31
    const int row   = rt * 32 + r;
    const int batch = bt * 8 + b8;

    float acc = bh[row] + g_xproj[(s * B_ + batch) * H_ + row];

    if (s > 0) {
        // Stage 8 hidden rows (coalesced: consecutive threads, consecutive cols)
        const int par = s & 1;
        #pragma unroll
        for (int i = 0; i < 16; i++) {
            int idx = t + 256 * i;        // 0..4095 over 8x512
            int b   = idx >> 9;
            int c   = idx & 511;
            hs[b * HS_STRIDE + c] = g_h[par][bt * 8 + b][c];
        }
        __syncthreads();

        #pragma unroll 8
        for (int k = 0; k < H_; k++)
            acc += hs[b8 * HS_STRIDE + k] * Wh[row * H_ + k];
    }

    float hv = 1.0f / (1.0f + __expf(-acc));
    g_h[(s + 1) & 1][batch][row] = hv;
    if (s == S_ - 1 && out_size >= B_ + B_ * H_)
        out[B_ + batch * H_ + row] = hv;   // hidden block of the output
}

// ---------------------------------------------------------------------------
// Final head: sig[b] = sigmoid(hidden[b] . Wf[0] + bf[0]).
// Final hidden lives in g_h[0] (parity (511+1)&1 == 0).
// Shared-memory tree reduction, no shuffles.
// ---------------------------------------------------------------------------
__global__ __launch_bounds__(128) void head_kernel(
    const float* __restrict__ Wf,
    const float* __restrict__ bf,
    float* __restrict__ out)
{
    __shared__ float red[128];
    const int b = blockIdx.x;
    const int t = threadIdx.x;

    float part = 0.0f;
    #pragma unroll
    for (int i = 0; i < 4; i++) {
        int k = t + 128 * i;
        part += g_h[0][b][k] * Wf[k];
    }
    red[t] = part;
    __syncthreads();

    for (int off = 64; off > 0; off >>= 1) {
        if (t < off) red[t] = red[t] + red[t + off];
        __syncthreads();
    }
    if (t == 0)
        out[b] = 1.0f / (1.0f + __expf(-(red[0] + bf[0])));
}

// ---------------------------------------------------------------------------
extern "C" void kernel_launch(void* const* d_in, const int* in_sizes, int n_in,
                              void* d_out, int out_size) {
    const int*   words = (const int*)d_in[0];   // int32 or int64 (auto-detected)
    const float* emb = (const float*)d_in[1];
    const float* Wh  = (const float*)d_in[2];
    const float* bh  = (const float*)d_in[3];
    const float* Wi  = (const float*)d_in[4];
    const float* bi  = (const float*)d_in[5];
    const float* Wf  = (const float*)d_in[6];
    const float* bf  = (const float*)d_in[7];
    float* out = (float*)d_out;

    dim3 gA(H_ / 64, (S_ * B_) / 64);          // (8, 512)
    xproj_kernel<<<gA, 256>>>(words, emb, Wi, bi);

    dim3 gB(8, 16);                            // 128 CTAs per step
    for (int s = 0; s < S_; s++)
        step_kernel<<<gB, 256>>>(Wh, bh, out, out_size, s);

    head_kernel<<<B_, 128>>>(Wf, bf, out);
}

// round 12
// speedup vs baseline: 1.8829x; 1.8829x over previous
#include <cuda_runtime.h>

// Problem constants
#define B_  64
#define S_  512
#define E_  256
#define H_  512
#define V_  50257
#define NCTA 128
#define PADH 516   // hs row stride: 516 mod 32 == 4 -> XOR-batch LDS.128 is conflict-free

// Scratch: device globals (the sanctioned allocation-free scratch)
__device__ float g_xproj[S_ * B_ * H_];     // [S][B][H]
__device__ float g_h[2][B_][H_];            // ping-pong hidden state
__device__ unsigned int g_count = 0;
__device__ unsigned int g_gen = 0;

// ---------------------------------------------------------------------------
// Word fetch: buffer may be int64 (reference dtype) or int32 (JAX x64 off).
// Odd 32-bit halves all zero across 4 samples => little-endian int64 layout.
// ---------------------------------------------------------------------------
__device__ __forceinline__ int words_is64(const int* w32) {
    return (w32[1] == 0) & (w32[3] == 0) & (w32[5] == 0) & (w32[7] == 0);
}
__device__ __forceinline__ unsigned int word_at(const int* w32, int i, int is64) {
    return is64 ? (unsigned int)w32[2 * i] : (unsigned int)w32[i];
}

// ---------------------------------------------------------------------------
// Grid-wide sense-reversing barrier (128 CTAs, 1/SM -> single wave guaranteed)
// ---------------------------------------------------------------------------
__device__ __forceinline__ void grid_barrier() {
    __syncthreads();
    if (threadIdx.x == 0) {
        __threadfence();                       // publish my stores
        volatile unsigned int* genp = (volatile unsigned int*)&g_gen;
        unsigned int gen = *genp;
        if (atomicAdd(&g_count, 1u) == NCTA - 1) {
            g_count = 0;
            __threadfence();
            atomicAdd(&g_gen, 1u);             // release
        } else {
            while (*genp == gen) { __nanosleep(32); }
        }
        __threadfence();                       // acquire others' stores
    }
    __syncthreads();
}

// ---------------------------------------------------------------------------
// Phase A: xproj[s][b][h] = bi[h] + sum_e emb[words[b][s]][e] * Wi[h][e]
// Tiled GEMM 64x64, K=256 in 4 chunks. (Known-good from R11.)
// ---------------------------------------------------------------------------
__global__ __launch_bounds__(256) void xproj_kernel(
    const int* __restrict__ words,
    const float* __restrict__ emb,
    const float* __restrict__ Wi,
    const float* __restrict__ bi)
{
    __shared__ float As[64][65];
    __shared__ float Ws[64][65];
    __shared__ unsigned int wbase[64];

    const int t  = threadIdx.x;
    const int tx = t & 15;
    const int ty = t >> 4;
    const int h0 = blockIdx.x * 64;
    const int m0 = blockIdx.y * 64;

    if (t < 64) {
        int m = m0 + t;
        int s = m >> 6;
        int b = m & 63;            // m = s*64 + b
        int is64 = words_is64(words);
        unsigned int wid = word_at(words, b * S_ + s, is64);
        if (wid >= V_) wid = 0;
        wbase[t] = wid * E_;
    }
    __syncthreads();

    float acc[4][4];
    #pragma unroll
    for (int i = 0; i < 4; i++)
        #pragma unroll
        for (int j = 0; j < 4; j++)
            acc[i][j] = 0.0f;

    for (int ec = 0; ec < 4; ec++) {
        #pragma unroll
        for (int i = 0; i < 16; i++) {
            int idx = t + 256 * i;
            int rr  = idx >> 6;
            int cc  = idx & 63;
            As[rr][cc] = emb[wbase[rr] + ec * 64 + cc];
            Ws[rr][cc] = Wi[(h0 + rr) * E_ + ec * 64 + cc];
        }
        __syncthreads();

        #pragma unroll 8
        for (int e = 0; e < 64; e++) {
            float a0 = As[ty +  0][e];
            float a1 = As[ty + 16][e];
            float a2 = As[ty + 32][e];
            float a3 = As[ty + 48][e];
            float w0 = Ws[tx +  0][e];
            float w1 = Ws[tx + 16][e];
            float w2 = Ws[tx + 32][e];
            float w3 = Ws[tx + 48][e];
            acc[0][0] += a0 * w0; acc[0][1] += a0 * w1; acc[0][2] += a0 * w2; acc[0][3] += a0 * w3;
            acc[1][0] += a1 * w0; acc[1][1] += a1 * w1; acc[1][2] += a1 * w2; acc[1][3] += a1 * w3;
            acc[2][0] += a2 * w0; acc[2][1] += a2 * w1; acc[2][2] += a2 * w2; acc[2][3] += a2 * w3;
            acc[3][0] += a3 * w0; acc[3][1] += a3 * w1; acc[3][2] += a3 * w2; acc[3][3] += a3 * w3;
        }
        __syncthreads();
    }

    #pragma unroll
    for (int i = 0; i < 4; i++) {
        int m = m0 + ty + 16 * i;
        #pragma unroll
        for (int j = 0; j < 4; j++) {
            int h = h0 + tx + 16 * j;
            g_xproj[m * H_ + h] = acc[i][j] + bi[h];
        }
    }
}

// ---------------------------------------------------------------------------
// Phase B: persistent recurrent kernel, Wh in REGISTERS.
// 128 CTAs = 8 batch-tiles (8 batches) x 16 row-tiles (32 h-rows).
// Thread t: r = t>>3 (row in tile), cb = t&7 (64-col chunk).
// Each thread holds Wh[row, cb*64 .. cb*64+63] in 16 float4 registers.
// Per step: stage h[8][512] into smem, 8 independent partial dots (batch i^cb,
// conflict-free), butterfly shfl_xor all-reduce over the 8-lane group,
// sigmoid, store, grid barrier.
// ---------------------------------------------------------------------------
__global__ __launch_bounds__(256) void rnn_kernel(
    const float* __restrict__ Wh,
    const float* __restrict__ bh,
    const float* __restrict__ Wf,
    const float* __restrict__ bf,
    float* __restrict__ out, int out_size)
{
    __shared__ float hs[8 * PADH];   // 16,512 B

    const int t   = threadIdx.x;
    const int cta = blockIdx.x;
    const int bt  = cta & 7;         // batch tile
    const int rt  = cta >> 3;        // row tile
    const int r   = t >> 3;          // 0..31
    const int cb  = t & 7;           // column chunk 0..7
    const int row   = rt * 32 + r;
    const int batch = bt * 8 + cb;

    // Load this thread's 64 Wh weights into registers (auto LDG.128)
    float4 w4[16];
    {
        const float* wp = &Wh[row * H_ + cb * 64];
        #pragma unroll
        for (int i = 0; i < 16; i++) {
            w4[i].x = wp[i * 4 + 0];
            w4[i].y = wp[i * 4 + 1];
            w4[i].z = wp[i * 4 + 2];
            w4[i].w = wp[i * 4 + 3];
        }
    }
    const float bhv = bh[row];

    for (int s = 0; s < S_; s++) {
        float acc0 = bhv + g_xproj[(s * B_ + batch) * H_ + row];

        if (s > 0) {
            // Stage h (this batch-tile, 8x512) into shared, coalesced
            const int par = s & 1;
            #pragma unroll
            for (int i = 0; i < 16; i++) {
                int idx = t + 256 * i;        // 0..4095 over 8x512
                int b   = idx >> 9;
                int c   = idx & 511;
                hs[b * PADH + c] = g_h[par][bt * 8 + b][c];
            }
            __syncthreads();

            float acc[8];
            #pragma unroll
            for (int i = 0; i < 8; i++) acc[i] = 0.0f;

            #pragma unroll
            for (int j4 = 0; j4 < 16; j4++) {
                float4 w = w4[j4];
                #pragma unroll
                for (int i = 0; i < 8; i++) {
                    int base = (i ^ cb) * PADH + cb * 64 + j4 * 4;
                    acc[i] += w.x * hs[base + 0] + w.y * hs[base + 1]
                            + w.z * hs[base + 2] + w.w * hs[base + 3];
                }
            }
            // Butterfly all-reduce across the 8-lane group:
            // partner lane cb^m holds batch (i^m)^(cb^m) = i^cb in slot i^m.
            #pragma unroll
            for (int m = 1; m < 8; m <<= 1) {
                float tmp[8];
                #pragma unroll
                for (int i = 0; i < 8; i++)
                    tmp[i] = __shfl_xor_sync(0xffffffffu, acc[i ^ m], m);
                #pragma unroll
                for (int i = 0; i < 8; i++) acc[i] += tmp[i];
            }
            acc0 += acc[0];                    // slot 0 == batch cb
        }

        float hv = 1.0f / (1.0f + __expf(-acc0));
        g_h[(s + 1) & 1][batch][row] = hv;
        if (s == S_ - 1 && out_size >= B_ + B_ * H_)
            out[B_ + batch * H_ + row] = hv;   // hidden block of the output

        grid_barrier();                        // also fences hs reuse
    }

    // Final head: sig[b] = sigmoid(hidden[b] . Wf[0] + bf[0]).
    // Final hidden parity: (511+1)&1 == 0.
    if (rt == 0) {
        int bl = t >> 5, lane = t & 31;
        int bb = bt * 8 + bl;                  // 8 CTAs x 8 batches = 64
        float part = 0.0f;
        #pragma unroll 4
        for (int k = lane; k < H_; k += 32)
            part += g_h[0][bb][k] * Wf[k];
        #pragma unroll
        for (int o = 16; o > 0; o >>= 1)
            part += __shfl_down_sync(0xffffffffu, part, o);
        if (lane == 0)
            out[bb] = 1.0f / (1.0f + __expf(-(part + bf[0])));
    }
}

// ---------------------------------------------------------------------------
extern "C" void kernel_launch(void* const* d_in, const int* in_sizes, int n_in,
                              void* d_out, int out_size) {
    const int*   words = (const int*)d_in[0];   // int32 or int64 (auto-detected)
    const float* emb = (const float*)d_in[1];
    const float* Wh  = (const float*)d_in[2];
    const float* bh  = (const float*)d_in[3];
    const float* Wi  = (const float*)d_in[4];
    const float* bi  = (const float*)d_in[5];
    const float* Wf  = (const float*)d_in[6];
    const float* bf  = (const float*)d_in[7];
    float* out = (float*)d_out;

    dim3 gA(H_ / 64, (S_ * B_) / 64);          // (8, 512)
    xproj_kernel<<<gA, 256>>>(words, emb, Wi, bi);

    rnn_kernel<<<NCTA, 256>>>(Wh, bh, Wf, bf, out, out_size);
}

// round 13
// speedup vs baseline: 2.2724x; 1.2068x over previous
#include <cuda_runtime.h>

// Problem constants
#define B_  64
#define S_  512
#define E_  256
#define H_  512
#define V_  50257
#define STR 516     // hs row stride: 516 mod 32 == 4 -> XOR-batch access conflict-free

// Scratch: device globals (the sanctioned allocation-free scratch)
__device__ float g_xproj[S_ * B_ * H_];     // [S][B][H]
__device__ float g_h[2][B_][H_];            // ping-pong hidden state

// ---------------------------------------------------------------------------
// Word fetch: buffer may be int64 (reference dtype) or int32 (JAX x64 off).
// ---------------------------------------------------------------------------
__device__ __forceinline__ int words_is64(const int* w32) {
    return (w32[1] == 0) & (w32[3] == 0) & (w32[5] == 0) & (w32[7] == 0);
}
__device__ __forceinline__ unsigned int word_at(const int* w32, int i, int is64) {
    return is64 ? (unsigned int)w32[2 * i] : (unsigned int)w32[i];
}

// ---------------------------------------------------------------------------
// Phase A: xproj[s][b][h] = bi[h] + sum_e emb[words[b][s]][e] * Wi[h][e]
// Tiled GEMM 64x64, K=256 in 4 chunks. (Known-good.)
// ---------------------------------------------------------------------------
__global__ __launch_bounds__(256) void xproj_kernel(
    const int* __restrict__ words,
    const float* __restrict__ emb,
    const float* __restrict__ Wi,
    const float* __restrict__ bi)
{
    __shared__ float As[64][65];
    __shared__ float Ws[64][65];
    __shared__ unsigned int wbase[64];

    const int t  = threadIdx.x;
    const int tx = t & 15;
    const int ty = t >> 4;
    const int h0 = blockIdx.x * 64;
    const int m0 = blockIdx.y * 64;

    if (t < 64) {
        int m = m0 + t;
        int s = m >> 6;
        int b = m & 63;            // m = s*64 + b
        int is64 = words_is64(words);
        unsigned int wid = word_at(words, b * S_ + s, is64);
        if (wid >= V_) wid = 0;
        wbase[t] = wid * E_;
    }
    __syncthreads();

    float acc[4][4];
    #pragma unroll
    for (int i = 0; i < 4; i++)
        #pragma unroll
        for (int j = 0; j < 4; j++)
            acc[i][j] = 0.0f;

    for (int ec = 0; ec < 4; ec++) {
        #pragma unroll
        for (int i = 0; i < 16; i++) {
            int idx = t + 256 * i;
            int rr  = idx >> 6;
            int cc  = idx & 63;
            As[rr][cc] = emb[wbase[rr] + ec * 64 + cc];
            Ws[rr][cc] = Wi[(h0 + rr) * E_ + ec * 64 + cc];
        }
        __syncthreads();

        #pragma unroll 8
        for (int e = 0; e < 64; e++) {
            float a0 = As[ty +  0][e];
            float a1 = As[ty + 16][e];
            float a2 = As[ty + 32][e];
            float a3 = As[ty + 48][e];
            float w0 = Ws[tx +  0][e];
            float w1 = Ws[tx + 16][e];
            float w2 = Ws[tx + 32][e];
            float w3 = Ws[tx + 48][e];
            acc[0][0] += a0 * w0; acc[0][1] += a0 * w1; acc[0][2] += a0 * w2; acc[0][3] += a0 * w3;
            acc[1][0] += a1 * w0; acc[1][1] += a1 * w1; acc[1][2] += a1 * w2; acc[1][3] += a1 * w3;
            acc[2][0] += a2 * w0; acc[2][1] += a2 * w1; acc[2][2] += a2 * w2; acc[2][3] += a2 * w3;
            acc[3][0] += a3 * w0; acc[3][1] += a3 * w1; acc[3][2] += a3 * w2; acc[3][3] += a3 * w3;
        }
        __syncthreads();
    }

    #pragma unroll
    for (int i = 0; i < 4; i++) {
        int m = m0 + ty + 16 * i;
        #pragma unroll
        for (int j = 0; j < 4; j++) {
            int h = h0 + tx + 16 * j;
            g_xproj[m * H_ + h] = acc[i][j] + bi[h];
        }
    }
}

// ---------------------------------------------------------------------------
// Phase B: persistent recurrent kernel with HW cluster barriers.
// 128 CTAs = 16 batch-tiles (4 batches) x 8 row-tiles (64 rows).
// Cluster of 8 = the 8 row-tiles of ONE batch-tile -> the entire step
// dependency closes within a cluster; NO global barrier anywhere.
// Thread t: r = t>>2 (row in tile), cb = t&3 (128-col chunk).
// Each thread holds Wh[row, cb*128 .. +127] in 32 float4 registers.
// Per step: barrier.cluster.wait, stage h[4][512] (L2 via __ldcg), 4 partial
// dots (batch i^cb, conflict-free), 2-round shfl_xor butterfly, sigmoid,
// store, barrier.cluster.arrive (next xproj load issues inside the window).
// ---------------------------------------------------------------------------
__global__ __launch_bounds__(256, 1) __cluster_dims__(8, 1, 1)
void rnn_kernel(
    const float* __restrict__ Wh,
    const float* __restrict__ bh,
    float* __restrict__ out, int out_size)
{
    __shared__ float hs[4 * STR];    // 8,256 B

    const int t   = threadIdx.x;
    const int cta = blockIdx.x;
    const int bt  = cta >> 3;        // batch tile 0..15  (cluster id)
    const int rt  = cta & 7;         // row tile 0..7     (rank in cluster)
    const int r   = t >> 2;          // 0..63
    const int cb  = t & 3;           // column chunk 0..3
    const int row   = rt * 64 + r;
    const int batch = bt * 4 + cb;

    // Load this thread's 128 Wh weights into registers
    float4 w4[32];
    {
        const float* wp = &Wh[row * H_ + cb * 128];
        #pragma unroll
        for (int i = 0; i < 32; i++) {
            w4[i].x = wp[i * 4 + 0];
            w4[i].y = wp[i * 4 + 1];
            w4[i].z = wp[i * 4 + 2];
            w4[i].w = wp[i * 4 + 3];
        }
    }
    const float bhv = bh[row];

    for (int s = 0; s < S_; s++) {
        // xproj load issues here — overlaps the cluster-barrier wait below
        float acc0 = bhv + g_xproj[(s * B_ + batch) * H_ + row];

        if (s > 0) {
            // Wait for previous step's arrive (all 8 CTAs' h stores visible)
            asm volatile("barrier.cluster.wait.aligned;" ::: "memory");

            // Stage h (4 batches x 512) from L2, bypassing L1
            const int par = s & 1;
            #pragma unroll
            for (int i = 0; i < 8; i++) {
                int idx = t + 256 * i;        // 0..2047 over 4x512
                int b   = idx >> 9;
                int c   = idx & 511;
                hs[b * STR + c] = __ldcg(&g_h[par][bt * 4 + b][c]);
            }
            __syncthreads();

            float acc[4];
            #pragma unroll
            for (int i = 0; i < 4; i++) acc[i] = 0.0f;

            #pragma unroll
            for (int j4 = 0; j4 < 32; j4++) {
                float4 w = w4[j4];
                #pragma unroll
                for (int i = 0; i < 4; i++) {
                    int base = (i ^ cb) * STR + cb * 128 + j4 * 4;
                    acc[i] += w.x * hs[base + 0] + w.y * hs[base + 1]
                            + w.z * hs[base + 2] + w.w * hs[base + 3];
                }
            }
            // Butterfly all-reduce across the 4-lane column group:
            // partner lane cb^m holds batch (i^m)^(cb^m) = i^cb in slot i^m.
            #pragma unroll
            for (int m = 1; m < 4; m <<= 1) {
                float tmp[4];
                #pragma unroll
                for (int i = 0; i < 4; i++)
                    tmp[i] = __shfl_xor_sync(0xffffffffu, acc[i ^ m], m);
                #pragma unroll
                for (int i = 0; i < 4; i++) acc[i] += tmp[i];
            }
            acc0 += acc[0];                    // slot 0 == batch cb
        }

        float hv = 1.0f / (1.0f + __expf(-acc0));
        g_h[(s + 1) & 1][batch][row] = hv;
        if (s == S_ - 1 && out_size >= B_ + B_ * H_)
            out[B_ + batch * H_ + row] = hv;   // hidden block of the output

        // Publish this step (release); matching wait at top of next iteration
        asm volatile("barrier.cluster.arrive.aligned;" ::: "memory");
    }
    // Match the final arrive
    asm volatile("barrier.cluster.wait.aligned;" ::: "memory");
}

// ---------------------------------------------------------------------------
// Final head: sig[b] = sigmoid(hidden[b] . Wf[0] + bf[0]).
// Final hidden lives in g_h[0] (parity (511+1)&1 == 0).
// ---------------------------------------------------------------------------
__global__ __launch_bounds__(128) void head_kernel(
    const float* __restrict__ Wf,
    const float* __restrict__ bf,
    float* __restrict__ out)
{
    __shared__ float red[128];
    const int b = blockIdx.x;
    const int t = threadIdx.x;

    float part = 0.0f;
    #pragma unroll
    for (int i = 0; i < 4; i++) {
        int k = t + 128 * i;
        part += g_h[0][b][k] * Wf[k];
    }
    red[t] = part;
    __syncthreads();

    for (int off = 64; off > 0; off >>= 1) {
        if (t < off) red[t] = red[t] + red[t + off];
        __syncthreads();
    }
    if (t == 0)
        out[b] = 1.0f / (1.0f + __expf(-(red[0] + bf[0])));
}

// ---------------------------------------------------------------------------
extern "C" void kernel_launch(void* const* d_in, const int* in_sizes, int n_in,
                              void* d_out, int out_size) {
    const int*   words = (const int*)d_in[0];   // int32 or int64 (auto-detected)
    const float* emb = (const float*)d_in[1];
    const float* Wh  = (const float*)d_in[2];
    const float* bh  = (const float*)d_in[3];
    const float* Wi  = (const float*)d_in[4];
    const float* bi  = (const float*)d_in[5];
    const float* Wf  = (const float*)d_in[6];
    const float* bf  = (const float*)d_in[7];
    float* out = (float*)d_out;

    dim3 gA(H_ / 64, (S_ * B_) / 64);          // (8, 512)
    xproj_kernel<<<gA, 256>>>(words, emb, Wi, bi);

    rnn_kernel<<<128, 256>>>(Wh, bh, out, out_size);

    head_kernel<<<B_, 128>>>(Wf, bf, out);
}